// round 2
// baseline (speedup 1.0000x reference)
#include <cuda_runtime.h>
#include <cstdint>

// ---------------------------------------------------------------------------
// CodebookLayer: out[m] = codebook[argmin_c ||x[m] - codebook[c]||^2]
// argmin of d2  ==  argmax of (2*x.c - ||c||^2)   (x2 term constant per row)
//
// Pipeline (all graph-capturable, no allocs):
//   1) c2_kernel     : g_c2[c] = ||codebook[c]||^2
//   2) init_kernel   : g_best[m] = 0  (packed (ordered_score, inv_idx))
//   3) gemm_argmax   : fp32 SGEMM tile 128x128x16, fused epilogue argmax
//                      published via 64-bit atomicMax
//   4) gather_kernel : out[m] = codebook[best_idx(m)]
// ---------------------------------------------------------------------------

#define MAX_M 8192
#define MAX_C 8192

__device__ unsigned long long g_best[MAX_M];
__device__ float              g_c2[MAX_C];

#define BM 128
#define BN 128
#define BK 16
#define TM 8
#define TN 8
#define PAD 4
#define SMSTRIDE (BM + PAD)   // 132

// monotone map float -> uint32 preserving order
__device__ __forceinline__ unsigned ford(float f) {
    unsigned u = __float_as_uint(f);
    return (u & 0x80000000u) ? ~u : (u | 0x80000000u);
}

// -------------------------------- c2 ---------------------------------------
__global__ void c2_kernel(const float* __restrict__ cb, int C, int K) {
    int row  = blockIdx.x * (blockDim.x >> 5) + (threadIdx.x >> 5);
    int lane = threadIdx.x & 31;
    if (row >= C) return;
    const float4* p = reinterpret_cast<const float4*>(cb + (size_t)row * K);
    float s = 0.f;
    int n4 = K >> 2;
    for (int i = lane; i < n4; i += 32) {
        float4 v = p[i];
        s += v.x * v.x + v.y * v.y + v.z * v.z + v.w * v.w;
    }
    #pragma unroll
    for (int m = 16; m; m >>= 1) s += __shfl_xor_sync(0xffffffffu, s, m);
    if (lane == 0) g_c2[row] = s;
}

// -------------------------------- init -------------------------------------
__global__ void init_kernel(int M) {
    int i = blockIdx.x * blockDim.x + threadIdx.x;
    if (i < M) g_best[i] = 0ull;
}

// --------------------------- gemm + argmax ---------------------------------
__global__ __launch_bounds__(256) void gemm_argmax_kernel(
    const float* __restrict__ X,   // [M, K] row-major
    const float* __restrict__ Cb,  // [C, K] row-major
    int M, int C, int K)
{
    __shared__ float As[BK][SMSTRIDE];
    __shared__ float Bs[BK][SMSTRIDE];

    const int t  = threadIdx.x;           // 0..255
    const int ty = t >> 4;                // 0..15  (row group)
    const int tx = t & 15;                // 0..15  (col group)
    const int bm = blockIdx.y * BM;
    const int bn = blockIdx.x * BN;

    // load mapping: 128 rows x 16 k = 512 float4; 2 per thread
    const int lrow0 = t >> 2;             // 0..63
    const int lcol  = (t & 3) << 2;       // {0,4,8,12}

    float acc[TM][TN];
    #pragma unroll
    for (int i = 0; i < TM; i++)
        #pragma unroll
        for (int j = 0; j < TN; j++) acc[i][j] = 0.f;

    const float* Xb = X  + (size_t)bm * K;
    const float* Cbb = Cb + (size_t)bn * K;

    for (int k0 = 0; k0 < K; k0 += BK) {
        #pragma unroll
        for (int h = 0; h < 2; h++) {
            int row = lrow0 + h * 64;
            float4 va = *reinterpret_cast<const float4*>(Xb  + (size_t)row * K + k0 + lcol);
            As[lcol + 0][row] = va.x;
            As[lcol + 1][row] = va.y;
            As[lcol + 2][row] = va.z;
            As[lcol + 3][row] = va.w;
            float4 vb = *reinterpret_cast<const float4*>(Cbb + (size_t)row * K + k0 + lcol);
            Bs[lcol + 0][row] = vb.x;
            Bs[lcol + 1][row] = vb.y;
            Bs[lcol + 2][row] = vb.z;
            Bs[lcol + 3][row] = vb.w;
        }
        __syncthreads();

        #pragma unroll
        for (int k = 0; k < BK; k++) {
            float a[TM], b[TN];
            float4 a0 = *reinterpret_cast<const float4*>(&As[k][ty * TM]);
            float4 a1 = *reinterpret_cast<const float4*>(&As[k][ty * TM + 4]);
            float4 b0 = *reinterpret_cast<const float4*>(&Bs[k][tx * TN]);
            float4 b1 = *reinterpret_cast<const float4*>(&Bs[k][tx * TN + 4]);
            a[0]=a0.x; a[1]=a0.y; a[2]=a0.z; a[3]=a0.w;
            a[4]=a1.x; a[5]=a1.y; a[6]=a1.z; a[7]=a1.w;
            b[0]=b0.x; b[1]=b0.y; b[2]=b0.z; b[3]=b0.w;
            b[4]=b1.x; b[5]=b1.y; b[6]=b1.z; b[7]=b1.w;
            #pragma unroll
            for (int i = 0; i < TM; i++)
                #pragma unroll
                for (int j = 0; j < TN; j++)
                    acc[i][j] = fmaf(a[i], b[j], acc[i][j]);
        }
        __syncthreads();
    }

    // ---- epilogue: per-row argmax of (2*acc - c2) ----
    float c2v[TN];
    #pragma unroll
    for (int j = 0; j < TN; j++) c2v[j] = g_c2[bn + tx * TN + j];

    #pragma unroll
    for (int i = 0; i < TM; i++) {
        float bestv = -3.4e38f;
        int   bestc = bn + tx * TN;
        #pragma unroll
        for (int j = 0; j < TN; j++) {
            float s = 2.f * acc[i][j] - c2v[j];
            if (s > bestv) { bestv = s; bestc = bn + tx * TN + j; }
        }
        unsigned long long p =
            ((unsigned long long)ford(bestv) << 32) |
            (unsigned long long)(0x7FFFFFFFu - (unsigned)bestc);
        #pragma unroll
        for (int m = 8; m; m >>= 1) {
            unsigned long long q = __shfl_xor_sync(0xffffffffu, p, m);
            if (q > p) p = q;
        }
        if (tx == 0)
            atomicMax(&g_best[bm + ty * TM + i], p);
    }
}

// -------------------------------- gather -----------------------------------
__global__ void gather_kernel(const float* __restrict__ cb,
                              float* __restrict__ out, int K)
{
    int r = blockIdx.x;
    unsigned long long p = g_best[r];
    int c = (int)(0x7FFFFFFFu - (unsigned)(p & 0xFFFFFFFFull));
    const float4* src = reinterpret_cast<const float4*>(cb + (size_t)c * K);
    float4* dst = reinterpret_cast<float4*>(out + (size_t)r * K);
    int n4 = K >> 2;
    for (int i = threadIdx.x; i < n4; i += blockDim.x) dst[i] = src[i];
}

// -------------------------------- launch -----------------------------------
extern "C" void kernel_launch(void* const* d_in, const int* in_sizes, int n_in,
                              void* d_out, int out_size)
{
    const float* x  = (const float*)d_in[0];   // [B*S, D] = [8192, 1024]
    const float* cb = (const float*)d_in[1];   // [C, D]   = [8192, 1024]
    float* out = (float*)d_out;

    const int D = 1024;
    const int M = in_sizes[0] / D;
    const int C = in_sizes[1] / D;

    // 1) row norms of codebook
    {
        int warps_per_block = 8;
        int blocks = (C + warps_per_block - 1) / warps_per_block;
        c2_kernel<<<blocks, warps_per_block * 32>>>(cb, C, D);
    }
    // 2) reset argmax scratch
    init_kernel<<<(M + 255) / 256, 256>>>(M);

    // 3) fused GEMM + argmax
    dim3 grid(C / BN, M / BM);
    gemm_argmax_kernel<<<grid, 256>>>(x, cb, M, C, D);

    // 4) gather winning codebook rows
    gather_kernel<<<M, 256>>>(cb, out, D);
}

// round 4
// speedup vs baseline: 5.6022x; 5.6022x over previous
#include <cuda_runtime.h>
#include <cuda_bf16.h>
#include <cuda_fp16.h>
#include <cstdint>

// ---------------------------------------------------------------------------
// CodebookLayer: out[m] = codebook[argmax_c (2*x.c - ||c||^2)]
//
// Round 4 strategy (sm_100 plain target: no tcgen05, use mma.sync):
//   0) convert x, codebook to bf16 scratch
//   1) c2_kernel: fp32 codebook row norms
//   2) screen_gemm: bf16 mma.sync 128x128x32, cp.async 3-stage pipeline;
//      stores screened score (2*xc - c2 + 1024) as fp16 to g_scores
//   3) select_rescore: per row, candidates within MARGIN of row max get
//      exact fp64 rescoring; winner's codebook row copied to out
// ---------------------------------------------------------------------------

#define MDIM 8192
#define CDIM 8192
#define KDIM 1024

__device__ __half        g_scores[(size_t)MDIM * CDIM];   // 128 MB scratch
__device__ __nv_bfloat16 g_xb [(size_t)MDIM * KDIM];
__device__ __nv_bfloat16 g_cbb[(size_t)CDIM * KDIM];
__device__ float         g_c2[CDIM];

// ---------------- helpers ---------------------------------------------------
__device__ __forceinline__ uint32_t smem_u32(const void* p) {
    uint32_t a;
    asm("{ .reg .u64 t; cvta.to.shared.u64 t, %1; cvt.u32.u64 %0, t; }"
        : "=r"(a) : "l"(p));
    return a;
}
__device__ __forceinline__ void cp16(uint32_t s, const void* g) {
    asm volatile("cp.async.cg.shared.global [%0], [%1], 16;"
                 :: "r"(s), "l"(g) : "memory");
}
__device__ __forceinline__ void ldsm4(uint32_t* r, uint32_t addr) {
    asm volatile("ldmatrix.sync.aligned.m8n8.x4.shared.b16 {%0,%1,%2,%3}, [%4];"
        : "=r"(r[0]), "=r"(r[1]), "=r"(r[2]), "=r"(r[3]) : "r"(addr));
}
__device__ __forceinline__ void mma_bf16(float* d, const uint32_t* a,
                                         uint32_t b0, uint32_t b1) {
    asm volatile(
        "mma.sync.aligned.m16n8k16.row.col.f32.bf16.bf16.f32 "
        "{%0,%1,%2,%3}, {%4,%5,%6,%7}, {%8,%9}, {%0,%1,%2,%3};"
        : "+f"(d[0]), "+f"(d[1]), "+f"(d[2]), "+f"(d[3])
        : "r"(a[0]), "r"(a[1]), "r"(a[2]), "r"(a[3]), "r"(b0), "r"(b1));
}

// ---------------- kernel 0: fp32 -> bf16 ------------------------------------
__global__ void convert_kernel(const float* __restrict__ s,
                               __nv_bfloat16* __restrict__ d, int n) {
    int i = (blockIdx.x * blockDim.x + threadIdx.x) * 4;
    if (i >= n) return;
    float4 v = *reinterpret_cast<const float4*>(s + i);
    __nv_bfloat162 p0 = {__float2bfloat16(v.x), __float2bfloat16(v.y)};
    __nv_bfloat162 p1 = {__float2bfloat16(v.z), __float2bfloat16(v.w)};
    *reinterpret_cast<__nv_bfloat162*>(d + i)     = p0;
    *reinterpret_cast<__nv_bfloat162*>(d + i + 2) = p1;
}

// ---------------- kernel 1: codebook row norms -------------------------------
__global__ void c2_kernel(const float* __restrict__ cb, int C, int K) {
    int row  = blockIdx.x * (blockDim.x >> 5) + (threadIdx.x >> 5);
    int lane = threadIdx.x & 31;
    if (row >= C) return;
    const float4* p = reinterpret_cast<const float4*>(cb + (size_t)row * K);
    float s = 0.f;
    for (int i = lane; i < (K >> 2); i += 32) {
        float4 v = p[i];
        s += v.x * v.x + v.y * v.y + v.z * v.z + v.w * v.w;
    }
    #pragma unroll
    for (int m = 16; m; m >>= 1) s += __shfl_xor_sync(0xffffffffu, s, m);
    if (lane == 0) g_c2[row] = s;
}

// ---------------- kernel 2: bf16 screening GEMM ------------------------------
// BM=BN=128, BK=32, 256 thr (8 warps, 2x4), warp tile 64x32, 3-stage cp.async
#define STAGE_BYTES 16384          // A 8KB + B 8KB per stage

__device__ __forceinline__ void issue_stage(
    uint32_t sb, const __nv_bfloat16* Ag, const __nv_bfloat16* Bg,
    int s, int r0, int ch)
{
    int k0 = s * 32;
    uint32_t so = sb + (s % 3) * STAGE_BYTES;
    uint32_t sw = (uint32_t)(ch ^ ((r0 >> 1) & 3)) << 4;
    int row = r0;
    cp16(so +        row * 64 + sw, Ag + (size_t)row * KDIM + k0 + ch * 8);
    cp16(so + 8192 + row * 64 + sw, Bg + (size_t)row * KDIM + k0 + ch * 8);
    row = r0 + 64;                                   // same swizzle (64>>1 & 3 == 0)
    cp16(so +        row * 64 + sw, Ag + (size_t)row * KDIM + k0 + ch * 8);
    cp16(so + 8192 + row * 64 + sw, Bg + (size_t)row * KDIM + k0 + ch * 8);
    asm volatile("cp.async.commit_group;" ::: "memory");
}

__global__ __launch_bounds__(256, 2) void screen_gemm() {
    __shared__ __align__(128) char smem[3 * STAGE_BYTES];   // 48 KB
    const uint32_t sb = smem_u32(smem);

    const int t    = threadIdx.x;
    const int lane = t & 31;
    const int wid  = t >> 5;
    const int wm   = wid >> 2;          // 0..1
    const int wn   = wid & 3;           // 0..3
    const int bm   = blockIdx.y * 128;
    const int bn   = blockIdx.x * 128;

    const int r0 = t >> 2;              // 0..63
    const int ch = t & 3;

    const __nv_bfloat16* Ag = g_xb  + (size_t)bm * KDIM;
    const __nv_bfloat16* Bg = g_cbb + (size_t)bn * KDIM;

    issue_stage(sb, Ag, Bg, 0, r0, ch);
    issue_stage(sb, Ag, Bg, 1, r0, ch);

    float acc[4][4][4];
    #pragma unroll
    for (int i = 0; i < 4; i++)
        #pragma unroll
        for (int j = 0; j < 4; j++)
            #pragma unroll
            for (int k = 0; k < 4; k++) acc[i][j][k] = 0.f;

    for (int s = 0; s < KDIM / 32; s++) {
        asm volatile("cp.async.wait_group 1;" ::: "memory");
        __syncthreads();
        if (s + 2 < KDIM / 32) issue_stage(sb, Ag, Bg, s + 2, r0, ch);

        const uint32_t As = sb + (s % 3) * STAGE_BYTES;
        const uint32_t Bs = As + 8192;
        const int rbase = lane & 15;

        #pragma unroll
        for (int kk = 0; kk < 2; kk++) {
            const int cin = kk * 2 + (lane >> 4);
            uint32_t a[4][4], b[2][4];
            #pragma unroll
            for (int mi = 0; mi < 4; mi++) {
                int row = wm * 64 + mi * 16 + rbase;
                ldsm4(a[mi], As + row * 64 +
                      ((uint32_t)(cin ^ ((row >> 1) & 3)) << 4));
            }
            #pragma unroll
            for (int g = 0; g < 2; g++) {
                int row = wn * 32 + g * 16 + rbase;
                ldsm4(b[g], Bs + row * 64 +
                      ((uint32_t)(cin ^ ((row >> 1) & 3)) << 4));
            }
            #pragma unroll
            for (int mi = 0; mi < 4; mi++)
                #pragma unroll
                for (int ni = 0; ni < 4; ni++)
                    mma_bf16(acc[mi][ni], a[mi],
                             b[ni >> 1][ni & 1], b[ni >> 1][(ni & 1) + 2]);
        }
    }

    // epilogue: screened score = 2*xc - c2 + 1024 (bias keeps |s| small for fp16)
    #pragma unroll
    for (int ni = 0; ni < 4; ni++) {
        int n0 = bn + wn * 32 + ni * 8 + 2 * (lane & 3);
        float c2a = 1024.f - g_c2[n0];
        float c2b = 1024.f - g_c2[n0 + 1];
        #pragma unroll
        for (int mi = 0; mi < 4; mi++) {
            int m0 = bm + wm * 64 + mi * 16 + (lane >> 2);
            __half2 h0 = __floats2half2_rn(2.f * acc[mi][ni][0] + c2a,
                                           2.f * acc[mi][ni][1] + c2b);
            *reinterpret_cast<__half2*>(&g_scores[(size_t)m0 * CDIM + n0]) = h0;
            __half2 h1 = __floats2half2_rn(2.f * acc[mi][ni][2] + c2a,
                                           2.f * acc[mi][ni][3] + c2b);
            *reinterpret_cast<__half2*>(&g_scores[(size_t)(m0 + 8) * CDIM + n0]) = h1;
        }
    }
}

// ---------------- kernel 3: select + exact fp64 rescore ----------------------
#define MARGIN 6.0f
#define MAXCAND 128

__global__ __launch_bounds__(256) void select_rescore(
    const float* __restrict__ x, const float* __restrict__ cb,
    float* __restrict__ out)
{
    __shared__ float  xs[KDIM];
    __shared__ float  smax[8];
    __shared__ double sred[2][8];
    __shared__ int    cand[MAXCAND];
    __shared__ int    ncand;

    const int m    = blockIdx.x;
    const int t    = threadIdx.x;
    const int lane = t & 31;
    const int wrp  = t >> 5;

    // x row -> smem
    {
        const float4* src = reinterpret_cast<const float4*>(x + (size_t)m * KDIM);
        reinterpret_cast<float4*>(xs)[t] = src[t];   // 256 * 16B = 4KB
    }
    if (t == 0) ncand = 0;

    // scan screened scores
    const uint4* row = reinterpret_cast<const uint4*>(g_scores + (size_t)m * CDIM);
    uint4 v[4];
    float lmax = -3.4e38f;
    #pragma unroll
    for (int j = 0; j < 4; j++) {
        v[j] = row[t + 256 * j];
        const __half2* h = reinterpret_cast<const __half2*>(&v[j]);
        #pragma unroll
        for (int e = 0; e < 4; e++) {
            float2 f = __half22float2(h[e]);
            lmax = fmaxf(lmax, fmaxf(f.x, f.y));
        }
    }
    #pragma unroll
    for (int o = 16; o; o >>= 1)
        lmax = fmaxf(lmax, __shfl_xor_sync(0xffffffffu, lmax, o));
    if (lane == 0) smax[wrp] = lmax;
    __syncthreads();
    float rowmax = smax[0];
    #pragma unroll
    for (int w = 1; w < 8; w++) rowmax = fmaxf(rowmax, smax[w]);
    const float thresh = rowmax - MARGIN;

    // collect candidates
    #pragma unroll
    for (int j = 0; j < 4; j++) {
        const __half2* h = reinterpret_cast<const __half2*>(&v[j]);
        #pragma unroll
        for (int e = 0; e < 4; e++) {
            float2 f = __half22float2(h[e]);
            int base = (t + 256 * j) * 8 + e * 2;
            if (f.x > thresh) { int p = atomicAdd(&ncand, 1); if (p < MAXCAND) cand[p] = base; }
            if (f.y > thresh) { int p = atomicAdd(&ncand, 1); if (p < MAXCAND) cand[p] = base + 1; }
        }
    }
    __syncthreads();
    int nc = min(ncand, MAXCAND);

    // exact fp64 rescore of each candidate
    double bestS = -1e300;
    int    bestI = 0x7FFFFFFF;
    for (int ci = 0; ci < nc; ci++) {
        int c = cand[ci];
        const float* crow = cb + (size_t)c * KDIM;
        double s = 0.0, cc = 0.0;
        for (int d = t; d < KDIM; d += 256) {
            double cv = (double)crow[d];
            s  += (double)xs[d] * cv;
            cc += cv * cv;
        }
        #pragma unroll
        for (int o = 16; o; o >>= 1) {
            s  += __shfl_xor_sync(0xffffffffu, s,  o);
            cc += __shfl_xor_sync(0xffffffffu, cc, o);
        }
        if (lane == 0) { sred[0][wrp] = s; sred[1][wrp] = cc; }
        __syncthreads();
        double st = 0.0, ct = 0.0;
        #pragma unroll
        for (int w = 0; w < 8; w++) { st += sred[0][w]; ct += sred[1][w]; }
        __syncthreads();
        double sc = 2.0 * st - ct;
        if (sc > bestS || (sc == bestS && c < bestI)) { bestS = sc; bestI = c; }
    }

    // copy winning codebook row to output
    const float4* src = reinterpret_cast<const float4*>(cb + (size_t)bestI * KDIM);
    float4* dst = reinterpret_cast<float4*>(out + (size_t)m * KDIM);
    dst[t] = src[t];
}

// ---------------- launch ------------------------------------------------------
extern "C" void kernel_launch(void* const* d_in, const int* in_sizes, int n_in,
                              void* d_out, int out_size)
{
    const float* x  = (const float*)d_in[0];   // [8192, 1024]
    const float* cb = (const float*)d_in[1];   // [8192, 1024]
    float* out = (float*)d_out;

    const int NX = MDIM * KDIM;
    const int NC = CDIM * KDIM;

    __nv_bfloat16 *xb_p = nullptr, *cb_p = nullptr;
    cudaGetSymbolAddress((void**)&xb_p, g_xb);
    cudaGetSymbolAddress((void**)&cb_p, g_cbb);

    convert_kernel<<<NX / 1024, 256>>>(x,  xb_p, NX);
    convert_kernel<<<NC / 1024, 256>>>(cb, cb_p, NC);
    c2_kernel<<<CDIM / 8, 256>>>(cb, CDIM, KDIM);

    dim3 grid(CDIM / 128, MDIM / 128);
    screen_gemm<<<grid, 256>>>();

    select_rescore<<<MDIM, 256>>>(x, cb, out);
}